// round 17
// baseline (speedup 1.0000x reference)
#include <cuda_runtime.h>
#include <cuda_fp16.h>
#include <cstdint>

// Problem constants
#define BATCH 2
#define SEQ   2048
#define HID   1024
#define NHEAD 16
#define HDIM  64
#define ROWS  (BATCH * SEQ)      // 4096

// ---------------- scratch (static device allocations; no cudaMalloc) --------
__device__ __half g_h16 [ROWS * HID];        // h fp16
__device__ __half g_hT  [BATCH * HID * SEQ]; // h^T fp16: [b*1024+c][m]
__device__ __half g_Wkvh[2048 * HID];        // [Wk;Wv] fp16
__device__ __half g_WqT [HID * HID];         // Wq^T fp16
__device__ __half g_G   [BATCH * HID * HID]; // G_b = h^T h (fp16)
__device__ __half g_T   [BATCH * HID * HID]; // T = Wk G_b
__device__ float  g_S   [BATCH * NHEAD * HDIM * HDIM];
__device__ __half g_U   [BATCH * HID * HID]; // g_U[b*1024+j][t] = U_b[t,j]
__device__ __half g_W2  [BATCH * HID * HID]; // W2_b[j][c]

// ---------------- helpers ----------------------------------------------------
__device__ __forceinline__ uint32_t smem_u32(const void* p) {
    uint32_t a;
    asm("{ .reg .u64 t; cvta.to.shared.u64 t, %1; cvt.u32.u64 %0, t; }"
        : "=r"(a) : "l"(p));
    return a;
}
__device__ __forceinline__ void cp16(uint32_t dst, const void* src) {
    asm volatile("cp.async.cg.shared.global [%0], [%1], 16;"
                 :: "r"(dst), "l"(src));
}

// ---- one fused conversion kernel (validated R14) ----------------------------
__global__ void cvtAll_kernel(const float* __restrict__ h,
                              const float* __restrict__ Wk,
                              const float* __restrict__ Wv,
                              const float* __restrict__ Wq) {
    __shared__ float tile[32][33];
    int blk = blockIdx.x;
    int tid = threadIdx.x;
    int tx = tid & 31, ty = tid >> 5;    // (32, 8)
    if (blk < 4096) {
        int c0  = (blk & 31) * 32;
        int gm0 = (blk >> 5) * 32;
#pragma unroll
        for (int i = 0; i < 32; i += 8) {
            float v = h[(size_t)(gm0 + ty + i) * HID + c0 + tx];
            tile[ty + i][tx] = v;
            g_h16[(size_t)(gm0 + ty + i) * HID + c0 + tx] = __float2half_rn(v);
        }
        __syncthreads();
        int b  = gm0 >> 11;
        int ml = gm0 & 2047;
#pragma unroll
        for (int i = 0; i < 32; i += 8)
            g_hT[((size_t)b * HID + c0 + ty + i) * SEQ + ml + tx] =
                __float2half_rn(tile[tx][ty + i]);
    } else if (blk < 6144) {
        int blk2 = blk - 4096;
        int sel = blk2 >> 10;
        int row = blk2 & 1023;
        const float* src = (sel == 0) ? Wk : Wv;
        __half* dst = g_Wkvh + ((size_t)sel * HID + row) * HID;
        int c4 = tid * 4;
        float4 v = *(const float4*)(src + (size_t)row * HID + c4);
        unsigned s0 = __half_as_ushort(__float2half_rn(v.x));
        unsigned s1 = __half_as_ushort(__float2half_rn(v.y));
        unsigned s2 = __half_as_ushort(__float2half_rn(v.z));
        unsigned s3 = __half_as_ushort(__float2half_rn(v.w));
        *(uint2*)((unsigned short*)dst + c4) =
            make_uint2(s0 | (s1 << 16), s2 | (s3 << 16));
    } else {
        int blk2 = blk - 6144;           // 0..1023
        int bx = (blk2 & 31) * 32, by = (blk2 >> 5) * 32;
#pragma unroll
        for (int i = 0; i < 32; i += 8)
            tile[ty + i][tx] = Wq[(size_t)(by + ty + i) * HID + bx + tx];
        __syncthreads();
#pragma unroll
        for (int i = 0; i < 32; i += 8)
            g_WqT[(size_t)(bx + ty + i) * HID + by + tx] =
                __float2half_rn(tile[tx][ty + i]);
    }
}

// ---------------- fp16 GEMM via mma.sync (m16n8k16) — proven R11 config ------
// C = A x B^T. CTA 128x128, 16 warps (4m x 4n), warp tile 32x32, 4-stage.
// A row wraps modulo amod; B advances bstride per (1<<bshift) A-rows.
// fp16out -> Ch (ld 1024); else fp32 -> Cf (ld ldc).
#define LDB    80
#define ASZ    10240
#define STAGE  20480
#define NSTG   4
#define GSMEM  (NSTG * STAGE)    // 81920

__global__ __launch_bounds__(512, 2)
void gemm_fp16(const __half* __restrict__ A,
               const __half* __restrict__ B,
               float* __restrict__ Cf, int ldc,
               __half* __restrict__ Ch, int fp16out,
               int kwords, int nit, int amod, int bshift, size_t bstride) {
    extern __shared__ char sm[];
    const int tid = threadIdx.x, lane = tid & 31, wid = tid >> 5;
    const int wm = wid & 3, wn = wid >> 2;
    const int bm = blockIdx.y * 128, bn = blockIdx.x * 128;
    const uint32_t sb = smem_u32(sm);
    const size_t rowb = (size_t)kwords * 2;
    const char* Ag = (const char*)A + (size_t)(bm % amod) * rowb;
    const char* Bg = (const char*)(B + (size_t)(bm >> bshift) * bstride) +
                     (size_t)bn * rowb;

    float acc[2][4][4];
#pragma unroll
    for (int mt = 0; mt < 2; ++mt)
#pragma unroll
        for (int nt = 0; nt < 4; ++nt)
#pragma unroll
            for (int j = 0; j < 4; ++j) acc[mt][nt][j] = 0.0f;

    const int lr = tid >> 2, lc = (tid & 3) * 16;

    auto load_stage = [&](int it) {
        int s = it & (NSTG - 1);
        size_t kb = (size_t)it * 64;
        uint32_t da = sb + s * STAGE, db = da + ASZ;
        cp16(da + lr * LDB + lc, Ag + kb + (size_t)lr * rowb + lc);
        cp16(db + lr * LDB + lc, Bg + kb + (size_t)lr * rowb + lc);
        asm volatile("cp.async.commit_group;" ::: "memory");
    };

    load_stage(0);
    load_stage(1);
    load_stage(2);

    for (int it = 0; it < nit; ++it) {
        if (it < nit - 1) asm volatile("cp.async.wait_group 2;" ::: "memory");
        else              asm volatile("cp.async.wait_group 0;" ::: "memory");
        __syncthreads();
        if (it + 3 < nit) load_stage(it + 3);

        int s = it & (NSTG - 1);
        uint32_t abase = sb + s * STAGE +
                         (wm * 32 + (lane & 15)) * LDB + ((lane >> 4) & 1) * 16;
        uint32_t bbase = sb + s * STAGE + ASZ +
                         (wn * 32 + (lane & 7) + ((lane >> 3) & 1) * 8) * LDB +
                         ((lane >> 4) & 1) * 16;
#pragma unroll
        for (int ks = 0; ks < 2; ++ks) {
            uint32_t a[2][4], b[4][2];
#pragma unroll
            for (int mt = 0; mt < 2; ++mt)
                asm volatile(
                    "ldmatrix.sync.aligned.m8n8.x4.shared.b16 {%0,%1,%2,%3}, [%4];"
                    : "=r"(a[mt][0]), "=r"(a[mt][1]), "=r"(a[mt][2]), "=r"(a[mt][3])
                    : "r"(abase + ks * 32 + mt * (16 * LDB)));
#pragma unroll
            for (int g = 0; g < 2; ++g)
                asm volatile(
                    "ldmatrix.sync.aligned.m8n8.x4.shared.b16 {%0,%1,%2,%3}, [%4];"
                    : "=r"(b[2 * g][0]), "=r"(b[2 * g + 1][0]),
                      "=r"(b[2 * g][1]), "=r"(b[2 * g + 1][1])
                    : "r"(bbase + ks * 32 + g * (16 * LDB)));
#pragma unroll
            for (int mt = 0; mt < 2; ++mt)
#pragma unroll
                for (int nt = 0; nt < 4; ++nt)
                    asm volatile(
                        "mma.sync.aligned.m16n8k16.row.col.f32.f16.f16.f32 "
                        "{%0,%1,%2,%3}, {%4,%5,%6,%7}, {%8,%9}, {%0,%1,%2,%3};"
                        : "+f"(acc[mt][nt][0]), "+f"(acc[mt][nt][1]),
                          "+f"(acc[mt][nt][2]), "+f"(acc[mt][nt][3])
                        : "r"(a[mt][0]), "r"(a[mt][1]), "r"(a[mt][2]), "r"(a[mt][3]),
                          "r"(b[nt][0]), "r"(b[nt][1]));
        }
    }

    if (fp16out) {
#pragma unroll
        for (int mt = 0; mt < 2; ++mt)
#pragma unroll
            for (int nt = 0; nt < 4; ++nt) {
                int r0 = bm + wm * 32 + mt * 16 + (lane >> 2);
                int c0 = bn + wn * 32 + nt * 8 + (lane & 3) * 2;
                *(__half2*)(Ch + (size_t)r0 * HID + c0) =
                    __floats2half2_rn(acc[mt][nt][0], acc[mt][nt][1]);
                *(__half2*)(Ch + (size_t)(r0 + 8) * HID + c0) =
                    __floats2half2_rn(acc[mt][nt][2], acc[mt][nt][3]);
            }
    } else {
#pragma unroll
        for (int mt = 0; mt < 2; ++mt)
#pragma unroll
            for (int nt = 0; nt < 4; ++nt) {
                int r0 = bm + wm * 32 + mt * 16 + (lane >> 2);
                int c0 = bn + wn * 32 + nt * 8 + (lane & 3) * 2;
                *(float2*)(Cf + (size_t)r0 * ldc + c0) =
                    make_float2(acc[mt][nt][0], acc[mt][nt][1]);
                *(float2*)(Cf + (size_t)(r0 + 8) * ldc + c0) =
                    make_float2(acc[mt][nt][2], acc[mt][nt][3]);
            }
    }
}

// ---- S_h[e,d] = sum_c2 T[(b,h*64+e)][c2] * Wv[(h*64+d)][c2] ----------------
// Proven scalar algorithm; re-tiled: chunk 32, grid (32, 32) for occupancy.
__global__ __launch_bounds__(256)
void s2_kernel() {
    const int bh = blockIdx.x;
    const int b  = bh / NHEAD;
    const int h  = bh % NHEAD;
    const int cbase = blockIdx.y * 32;

    __shared__ float Ts[64][33];
    __shared__ float Vs[64][33];

    const int tid = threadIdx.x;

    const unsigned short* Tg = (const unsigned short*)g_T +
        ((size_t)b * HID + h * HDIM) * HID + cbase;
    const unsigned short* Vg = (const unsigned short*)g_Wkvh +
        ((size_t)(1024 + h * HDIM)) * HID + cbase;
#pragma unroll
    for (int itq = 0; itq < 2; ++itq) {
        int q = tid + itq * 256;        // 0..511 quad index
        int row = q >> 3;               // 0..63
        int qc = (q & 7) * 4;           // 0..28
        uint2 tv = *(const uint2*)(Tg + (size_t)row * HID + qc);
        uint2 vv = *(const uint2*)(Vg + (size_t)row * HID + qc);
        Ts[row][qc + 0] = __half2float(__ushort_as_half((unsigned short)(tv.x)));
        Ts[row][qc + 1] = __half2float(__ushort_as_half((unsigned short)(tv.x >> 16)));
        Ts[row][qc + 2] = __half2float(__ushort_as_half((unsigned short)(tv.y)));
        Ts[row][qc + 3] = __half2float(__ushort_as_half((unsigned short)(tv.y >> 16)));
        Vs[row][qc + 0] = __half2float(__ushort_as_half((unsigned short)(vv.x)));
        Vs[row][qc + 1] = __half2float(__ushort_as_half((unsigned short)(vv.x >> 16)));
        Vs[row][qc + 2] = __half2float(__ushort_as_half((unsigned short)(vv.y)));
        Vs[row][qc + 3] = __half2float(__ushort_as_half((unsigned short)(vv.y >> 16)));
    }
    __syncthreads();

    const int t1 = (tid >> 4) * 4;
    const int t2 = (tid & 15) * 4;

    float acc[4][4];
#pragma unroll
    for (int i = 0; i < 4; ++i)
#pragma unroll
        for (int j = 0; j < 4; ++j) acc[i][j] = 0.0f;

#pragma unroll 8
    for (int cc = 0; cc < 32; ++cc) {
        float a[4], v[4];
#pragma unroll
        for (int i = 0; i < 4; ++i) a[i] = Ts[t1 + i][cc];
#pragma unroll
        for (int j = 0; j < 4; ++j) v[j] = Vs[t2 + j][cc];
#pragma unroll
        for (int i = 0; i < 4; ++i)
#pragma unroll
            for (int j = 0; j < 4; ++j)
                acc[i][j] = fmaf(a[i], v[j], acc[i][j]);
    }

    float* Sb = g_S + (size_t)bh * HDIM * HDIM;
#pragma unroll
    for (int i = 0; i < 4; ++i)
#pragma unroll
        for (int j = 0; j < 4; ++j)
            atomicAdd(&Sb[(t1 + i) * HDIM + t2 + j], acc[i][j]);
}

// ---- g_U[b*1024+j][h*64+e] = sum_d S_h[e,d]*Wo[j,h*64+d]  (fp16) -----------
__global__ __launch_bounds__(256)
void u_kernel(const float* __restrict__ Wo) {
    const int bh = blockIdx.x;
    const int b  = bh / NHEAD;
    const int h  = bh % NHEAD;
    const int jbase = blockIdx.y * 128;

    __shared__ float Ss[HDIM][HDIM + 1];
    const int tid = threadIdx.x;
    {
        const float* Sb = g_S + (size_t)bh * HDIM * HDIM;
#pragma unroll
        for (int it = 0; it < 4; ++it) {
            int idx = tid + it * 256;
            int row = idx >> 4;
            int c4  = (idx & 15) * 4;
            float4 v = *(const float4*)(Sb + row * HDIM + c4);
            Ss[row][c4 + 0] = v.x; Ss[row][c4 + 1] = v.y;
            Ss[row][c4 + 2] = v.z; Ss[row][c4 + 3] = v.w;
        }
    }
    __syncthreads();

    const int jloc = tid >> 1;
    const int eh = (tid & 1) * 32;
    const int j = jbase + jloc;
    const float* wrow = Wo + (size_t)j * HID + h * HDIM;

    float acc[32];
#pragma unroll
    for (int e = 0; e < 32; ++e) acc[e] = 0.0f;

#pragma unroll
    for (int d4 = 0; d4 < HDIM; d4 += 4) {
        float4 w = *(const float4*)(wrow + d4);
#pragma unroll
        for (int e = 0; e < 32; ++e) {
            float s = fmaf(w.x, Ss[eh + e][d4 + 0],
                      fmaf(w.y, Ss[eh + e][d4 + 1],
                      fmaf(w.z, Ss[eh + e][d4 + 2],
                           w.w * Ss[eh + e][d4 + 3])));
            acc[e] += s;
        }
    }

    unsigned short* dst = (unsigned short*)g_U +
        ((size_t)b * HID + j) * HID + h * HDIM + eh;
#pragma unroll
    for (int q = 0; q < 4; ++q) {
        unsigned p[4];
#pragma unroll
        for (int t = 0; t < 4; ++t) {
            unsigned lo2 = __half_as_ushort(__float2half_rn(acc[q * 8 + t * 2]));
            unsigned hi2 = __half_as_ushort(__float2half_rn(acc[q * 8 + t * 2 + 1]));
            p[t] = lo2 | (hi2 << 16);
        }
        *(uint4*)(dst + q * 8) = make_uint4(p[0], p[1], p[2], p[3]);
    }
}

// ---------------- launch ----------------------------------------------------
extern "C" void kernel_launch(void* const* d_in, const int* in_sizes, int n_in,
                              void* d_out, int out_size) {
    (void)in_sizes; (void)n_in; (void)out_size;
    const float* h   = (const float*)d_in[0];
    const float* Wq  = (const float*)d_in[1];
    const float* Wk  = (const float*)d_in[2];
    const float* Wv  = (const float*)d_in[3];
    // d_in[4] = Wspan (dead code in reference)
    const float* Wo  = (const float*)d_in[5];
    float* out = (float*)d_out;

    __half *pH16, *pHT, *pWkvh, *pWqT, *pG, *pT, *pU, *pW2;
    float *pS;
    cudaGetSymbolAddress((void**)&pH16,  g_h16);
    cudaGetSymbolAddress((void**)&pHT,   g_hT);
    cudaGetSymbolAddress((void**)&pWkvh, g_Wkvh);
    cudaGetSymbolAddress((void**)&pWqT,  g_WqT);
    cudaGetSymbolAddress((void**)&pG,    g_G);
    cudaGetSymbolAddress((void**)&pT,    g_T);
    cudaGetSymbolAddress((void**)&pU,    g_U);
    cudaGetSymbolAddress((void**)&pW2,   g_W2);
    cudaGetSymbolAddress((void**)&pS,    g_S);

    cudaFuncSetAttribute(gemm_fp16,
                         cudaFuncAttributeMaxDynamicSharedMemorySize, GSMEM);

    const int BIG = 1 << 30;

    // 0) zero S first (overlaps behind conversions in issue order)
    cudaMemsetAsync(pS, 0, (size_t)BATCH * NHEAD * HDIM * HDIM * sizeof(float));

    // 1) all conversions in one kernel
    cvtAll_kernel<<<7168, 256>>>(h, Wk, Wv, Wq);

    // 2) G_b = h_b^T h_b  (fp16 out)
    gemm_fp16<<<dim3(8, 16), 512, GSMEM>>>(
        pHT, pHT, nullptr, 0, pG, 1, SEQ, 64, BIG, 10, (size_t)HID * SEQ);

    // 3) T = Wk G_b
    gemm_fp16<<<dim3(8, 16), 512, GSMEM>>>(
        pWkvh, pG, nullptr, 0, pT, 1, HID, 32, HID, 10, (size_t)HID * HID);

    // 4) S_h = T_h Wv_h^T  (scalar, atomic; chunk 32 for occupancy)
    s2_kernel<<<dim3(BATCH * NHEAD, 32), 256>>>();

    // 5) U_b = S_h Wo_h^T folded (fp16, A-layout)
    u_kernel<<<dim3(BATCH * NHEAD, 8), 256>>>(Wo);

    // 6) W2_b[j][c] = sum_t U_b[t,j] Wq[t,c]
    gemm_fp16<<<dim3(8, 16), 512, GSMEM>>>(
        pU, pWqT, nullptr, 0, pW2, 1, HID, 32, BIG, 10, 0);

    // 7) out = h16 @ W2_b^T  (per-batch B)
    gemm_fp16<<<dim3(8, 32), 512, GSMEM>>>(
        pH16, pW2, out, 1024, nullptr, 0, HID, 32, BIG, 11, (size_t)HID * HID);
}